// round 14
// baseline (speedup 1.0000x reference)
#include <cuda_runtime.h>
#include <cuda_fp16.h>
#include <math.h>
#include <stdint.h>

namespace {
constexpr int B_ = 64;
constexpr int T_ = 512;
constexpr int I_ = 512;
constexpr int H_ = 1024;
constexpr int G_ = 3 * H_;     // 3072
constexpr int NBLK = 128;      // 2 mgroups x 64 colgroups
constexpr int NTHR = 256;
constexpr int BH = B_ * H_;

constexpr int WP = 516;        // W smem row pad (u32)
constexpr int HSP = 516;       // h slice row pad (u32)
constexpr int RPD = 50;        // reduce row pad (floats)
constexpr int WS_U = 48 * WP;
constexpr int HS_U = 32 * HSP;
constexpr int RED_U = 4 * 32 * RPD;
constexpr int REC_SMEM = (WS_U + HS_U + RED_U) * 4;   // 190720 bytes

constexpr int XG_ST = 3;                               // xg pipeline stages
constexpr int XG_SMEM = XG_ST * 128 * 20 * 4 * 2;      // 61440 bytes
}

// Scratch (device globals -- no runtime allocation)
__device__ float g_xg[(size_t)B_ * T_ * G_];            // xg (fp32)
__device__ __align__(16) uint32_t g_ah[(size_t)B_ * T_ * H_ / 2]; // layer input, fp16 pairs
__device__ __align__(16) uint32_t g_wh[(size_t)G_ * H_ / 2];      // w_ih fp16 pairs
__device__ __align__(16) uint32_t g_hh[BH];             // h fp16 pairs, ping-pong
__device__ unsigned g_barcnt[2 * T_];

// ---- helpers ----
__device__ __forceinline__ uint32_t pack2(float x, float y) {
    __half2 h = __floats2half2_rn(x, y);
    return *(uint32_t*)&h;
}
// m16n8k16 fp16 mma, fp32 accum
__device__ __forceinline__ void mma16(float* d, const uint32_t* a, const uint32_t* b) {
    asm volatile(
        "mma.sync.aligned.m16n8k16.row.col.f32.f16.f16.f32 "
        "{%0,%1,%2,%3}, {%4,%5,%6,%7}, {%8,%9}, {%0,%1,%2,%3};"
        : "+f"(d[0]), "+f"(d[1]), "+f"(d[2]), "+f"(d[3])
        : "r"(a[0]), "r"(a[1]), "r"(a[2]), "r"(a[3]), "r"(b[0]), "r"(b[1]));
}
__device__ __forceinline__ void ldsm4(uint32_t* r, uint32_t a) {
    asm volatile("ldmatrix.sync.aligned.m8n8.x4.shared.b16 {%0,%1,%2,%3}, [%4];"
                 : "=r"(r[0]), "=r"(r[1]), "=r"(r[2]), "=r"(r[3]) : "r"(a));
}
__device__ __forceinline__ uint32_t smem_u32(const void* p) {
    uint32_t a;
    asm("{ .reg .u64 t; cvta.to.shared.u64 t, %1; cvt.u32.u64 %0, t; }" : "=r"(a) : "l"(p));
    return a;
}
__device__ __forceinline__ void cp16(uint32_t d, const uint32_t* s) {
    asm volatile("cp.async.cg.shared.global [%0], [%1], 16;" :: "r"(d), "l"(s) : "memory");
}

// ---- grid barrier (128 arrivals). No explicit fence: bar.sync orders all
// block stores before tid0; red.release.gpu -> ld.acquire.gpu carries them
// to the consumer (valid PTX causality chain).
__device__ __forceinline__ void grid_bar(unsigned* cnt) {
    __syncthreads();
    if (threadIdx.x == 0) {
        asm volatile("red.release.gpu.global.add.u32 [%0], 1;" :: "l"(cnt) : "memory");
        unsigned v;
        do {
            asm volatile("ld.acquire.gpu.global.u32 %0, [%1];" : "=r"(v) : "l"(cnt) : "memory");
        } while (v < (unsigned)NBLK);
    }
    __syncthreads();
}

__global__ void reset_barriers() { g_barcnt[threadIdx.x] = 0; }

// ---- fp32 -> fp16 conversion (vectorized) ----
__global__ __launch_bounds__(256) void cvt16(const float* __restrict__ in,
                                             uint32_t* __restrict__ out, int n4) {
    int i = blockIdx.x * 256 + threadIdx.x;
    if (i < n4) {
        float4 v = ((const float4*)in)[i];
        ((uint2*)out)[i] = make_uint2(pack2(v.x, v.y), pack2(v.z, v.w));
    }
}

// ============================================================================
// xg = A[M][K] @ W[G][K]^T + b_ih (+ b_hh folded for r/z gates)
// fp16 mma m16n8k16, tile 128x128x32, 3-stage cp.async, ldmatrix frag loads.
// ============================================================================
__global__ __launch_bounds__(256) void xg_gemm(
    const uint32_t* __restrict__ A,   // [M][K/2]
    const uint32_t* __restrict__ W,   // [G][K/2]
    const float* __restrict__ bih, const float* __restrict__ bhh,
    int K)
{
    extern __shared__ uint32_t smu[];
    uint32_t* sA = smu;                      // [3][128][20]
    uint32_t* sB = smu + XG_ST * 128 * 20;   // [3][128][20]
    const uint32_t sA_b = smem_u32(sA);
    const uint32_t sB_b = smem_u32(sB);

    const int tid = threadIdx.x;
    const int lane = tid & 31, wid = tid >> 5;
    const int gq = lane >> 2, tig = lane & 3;
    const int wm = wid & 3, wn = wid >> 2;
    const int m0 = blockIdx.y * 128, n0 = blockIdx.x * 128;
    const int K2 = K >> 1;
    const int mrow = tid >> 1;
    const int kq = (tid & 1) * 8;

    float acc[2][8][4];
#pragma unroll
    for (int mi = 0; mi < 2; mi++)
#pragma unroll
        for (int ni = 0; ni < 8; ni++)
#pragma unroll
            for (int q = 0; q < 4; q++) acc[mi][ni][q] = 0.f;

    const int nch = K >> 5;                  // 32-k (16-u32) chunks
    const uint32_t dAoff = (uint32_t)((mrow * 20 + kq) * 4);

    auto issue = [&](int ch) {
        const int st = ch % XG_ST;
        const uint32_t sbase = (uint32_t)(st * 128 * 20 * 4);
        const uint32_t* sa = A + (size_t)(m0 + mrow) * K2 + ch * 16 + kq;
        const uint32_t* sb = W + (size_t)(n0 + mrow) * K2 + ch * 16 + kq;
        cp16(sA_b + sbase + dAoff, sa);
        cp16(sA_b + sbase + dAoff + 16, sa + 4);
        cp16(sB_b + sbase + dAoff, sb);
        cp16(sB_b + sbase + dAoff + 16, sb + 4);
        asm volatile("cp.async.commit_group;" ::: "memory");
    };

    issue(0);
    issue(1);

    // ldmatrix per-lane bases (bytes), verified mapping (R9 recurrence):
    // A x4 (per mi): lanes 0-15 -> rows mb+0..15 khalf0; 16-31 -> khalf1
    uint32_t aOff[2];
#pragma unroll
    for (int mi = 0; mi < 2; mi++)
        aOff[mi] = (uint32_t)(((wm * 32 + mi * 16 + (lane & 15)) * 20
                              + ((lane >> 4) << 2)) * 4);
    // B x4 (per ni-pair p): rows wn*64 + p*16 + (lane&7) + ((lane>>4)<<3),
    // khalf = (lane>>3)&1
    uint32_t bOff[4];
#pragma unroll
    for (int p = 0; p < 4; p++)
        bOff[p] = (uint32_t)(((wn * 64 + p * 16 + (lane & 7) + ((lane >> 4) << 3)) * 20
                             + (((lane >> 3) & 1) << 2)) * 4);

    for (int ch = 0; ch < nch; ch++) {
        if (ch + 1 < nch) asm volatile("cp.async.wait_group 1;" ::: "memory");
        else              asm volatile("cp.async.wait_group 0;" ::: "memory");
        __syncthreads();
        if (ch + 2 < nch) issue(ch + 2);

        const uint32_t abase = sA_b + (uint32_t)((ch % XG_ST) * 128 * 20 * 4);
        const uint32_t bbase = sB_b + (uint32_t)((ch % XG_ST) * 128 * 20 * 4);
#pragma unroll
        for (int s = 0; s < 2; s++) {
            const uint32_t soff = (uint32_t)(s * 32);   // 8 u32 per slot
            uint32_t af[2][4], bf[4][4];
            ldsm4(af[0], abase + aOff[0] + soff);
            ldsm4(af[1], abase + aOff[1] + soff);
#pragma unroll
            for (int p = 0; p < 4; p++)
                ldsm4(bf[p], bbase + bOff[p] + soff);
#pragma unroll
            for (int p = 0; p < 4; p++) {
                mma16(acc[0][2 * p],     af[0], bf[p]);
                mma16(acc[0][2 * p + 1], af[0], bf[p] + 2);
                mma16(acc[1][2 * p],     af[1], bf[p]);
                mma16(acc[1][2 * p + 1], af[1], bf[p] + 2);
            }
        }
        __syncthreads();
    }

#pragma unroll
    for (int mi = 0; mi < 2; mi++) {
        int m = m0 + wm * 32 + mi * 16 + gq;
#pragma unroll
        for (int ni = 0; ni < 8; ni++) {
            int n = n0 + wn * 64 + ni * 8 + 2 * tig;
            float b0 = bih[n], b1 = bih[n + 1];
            if (n < 2 * H_) { b0 += bhh[n]; b1 += bhh[n + 1]; }
            *(float2*)(g_xg + (size_t)m * G_ + n) =
                make_float2(acc[mi][ni][0] + b0, acc[mi][ni][1] + b1);
            *(float2*)(g_xg + (size_t)(m + 8) * G_ + n) =
                make_float2(acc[mi][ni][2] + b0, acc[mi][ni][3] + b1);
        }
    }
}

// ============================================================================
// Persistent recurrence (R8 structure — best measured config):
// 2D ownership (32 batch rows x 16 cols per block), W_hh slice in smem fp16,
// per step: 2 pipelined 32KB h halves via cp.async, scalar frag LDS,
// 4-way smem reduce, fp32 gates, 128-block grid barrier (fence-elided).
// ============================================================================
__global__ void __launch_bounds__(NTHR, 1) gru_rec(
    const float* __restrict__ Whh, const float* __restrict__ bhh,
    int layer, float* __restrict__ final_out)
{
    extern __shared__ uint32_t smu[];
    uint32_t* ws = smu;                    // [48][WP]
    uint32_t* hs = smu + WS_U;             // [32][HSP]
    float* red = (float*)(smu + WS_U + HS_U);  // [4][32][RPD]

    const int tid = threadIdx.x;
    const int lane = tid & 31, wid = tid >> 5;
    const int g = lane >> 2, tig = lane & 3;
    const int wk = wid & 3;        // k-quarter (slot interleave s%4==wk)
    const int wn = wid >> 2;       // n half (24 W rows)
    const int cg = blockIdx.x & 63;
    const int mg = blockIdx.x >> 6;
    const int j0 = cg * 16;        // owned cols [j0, j0+16)
    const int b0 = mg * 32;        // owned batch rows [b0, b0+32)
    const uint32_t hs_b = smem_u32(hs);

    // ---- stage W_hh slice (48 rows x 1024) into smem as fp16 (once) ----
    for (int f = tid; f < 48 * 256; f += NTHR) {
        int v = f >> 8, q = f & 255;
        int ni = v >> 4, jj = v & 15;
        const float* wr = Whh + (size_t)(ni * H_ + j0 + jj) * H_ + 4 * q;
        float4 w4 = *(const float4*)wr;
        *(uint2*)(ws + (size_t)v * WP + 2 * q) =
            make_uint2(pack2(w4.x, w4.y), pack2(w4.z, w4.w));
    }
    const int bloc = tid >> 3;                  // local batch row 0..31
    const int jj0 = (tid * 2) & 15;             // even col offset 0..14
    const float bhn0 = bhh[2 * H_ + j0 + jj0];
    const float bhn1 = bhh[2 * H_ + j0 + jj0 + 1];
    float hreg[2] = {0.f, 0.f};
    __syncthreads();

    unsigned* barBase = g_barcnt + layer * T_;
    const int srow = tid >> 3;                  // staging row 0..31
    const int sc0 = (tid & 7) * 4;              // staging u32 col base

    for (int t = 0; t < T_; t++) {
        // prefetch gate inputs (hide latency behind mma pipeline)
        const float* xp = g_xg + ((size_t)(b0 + bloc) * T_ + t) * G_ + j0 + jj0;
        float2 xr2 = *(const float2*)xp;
        float2 xz2 = *(const float2*)(xp + H_);
        float2 xn2 = *(const float2*)(xp + 2 * H_);

        float gr[2] = {0.f, 0.f}, gz[2] = {0.f, 0.f}, gn[2] = {0.f, 0.f};

        if (t > 0) {
            const uint32_t* hre = g_hh + (size_t)((t - 1) & 1) * (BH / 2)
                                  + (size_t)b0 * (H_ / 2);

            float acc[2][3][4];
#pragma unroll
            for (int mt = 0; mt < 2; mt++)
#pragma unroll
                for (int ni = 0; ni < 3; ni++)
#pragma unroll
                    for (int q = 0; q < 4; q++) acc[mt][ni][q] = 0.f;

            // issue both halves of the 32x512(u32) h slice
#pragma unroll
            for (int hh = 0; hh < 2; hh++) {
                uint32_t d = hs_b + (uint32_t)(srow * HSP + hh * 256 + sc0) * 4u;
                const uint32_t* s = hre + (size_t)srow * (H_ / 2) + hh * 256 + sc0;
#pragma unroll
                for (int r = 0; r < 8; r++) {
                    asm volatile("cp.async.cg.shared.global [%0], [%1], 16;"
                                 :: "r"(d + r * 128u), "l"(s + r * 32) : "memory");
                }
                asm volatile("cp.async.commit_group;" ::: "memory");
            }

#pragma unroll
            for (int hh = 0; hh < 2; hh++) {
                if (hh == 0) asm volatile("cp.async.wait_group 1;" ::: "memory");
                else         asm volatile("cp.async.wait_group 0;" ::: "memory");
                __syncthreads();

                // 8 k16 slots for this warp in this half: s = hh*32 + wk + 4*u
#pragma unroll
                for (int u = 0; u < 8; u++) {
                    const int s = hh * 32 + wk + 4 * u;
                    const int c0 = s * 8;
                    uint32_t af[2][4];
#pragma unroll
                    for (int mt = 0; mt < 2; mt++) {
                        const uint32_t* r0 = hs + (size_t)(mt * 16 + g) * HSP + c0 + tig;
                        const uint32_t* r1 = hs + (size_t)(mt * 16 + 8 + g) * HSP + c0 + tig;
                        af[mt][0] = r0[0];
                        af[mt][1] = r1[0];
                        af[mt][2] = r0[4];
                        af[mt][3] = r1[4];
                    }
#pragma unroll
                    for (int ni = 0; ni < 3; ni++) {
                        const uint32_t* br = ws + (size_t)(wn * 24 + ni * 8 + g) * WP + c0 + tig;
                        uint32_t bf[2] = {br[0], br[4]};
                        mma16(acc[0][ni], af[0], bf);
                        mma16(acc[1][ni], af[1], bf);
                    }
                }
            }

            // ---- 4-way k reduce via smem: red[wk][m][n] ----
#pragma unroll
            for (int mt = 0; mt < 2; mt++)
#pragma unroll
                for (int ni = 0; ni < 3; ni++) {
                    int n = wn * 24 + ni * 8 + 2 * tig;
                    float* p0 = red + (size_t)(wk * 32 + mt * 16 + g) * RPD + n;
                    *(float2*)p0 = make_float2(acc[mt][ni][0], acc[mt][ni][1]);
                    float* p1 = red + (size_t)(wk * 32 + mt * 16 + 8 + g) * RPD + n;
                    *(float2*)p1 = make_float2(acc[mt][ni][2], acc[mt][ni][3]);
                }
            __syncthreads();

#pragma unroll
            for (int e = 0; e < 2; e++) {
                int jj = jj0 + e;
#pragma unroll
                for (int p = 0; p < 4; p++) {
                    const float* rp = red + (size_t)(p * 32 + bloc) * RPD;
                    gr[e] += rp[jj];
                    gz[e] += rp[16 + jj];
                    gn[e] += rp[32 + jj];
                }
            }
        }

        // ---- gates: 2 adjacent cols per thread ----
        float hn0, hn1;
        {
            float r = 1.f / (1.f + expf(-(xr2.x + gr[0])));
            float z = 1.f / (1.f + expf(-(xz2.x + gz[0])));
            float n = tanhf(xn2.x + r * (gn[0] + bhn0));
            hn0 = (1.f - z) * n + z * hreg[0];
            hreg[0] = hn0;
        }
        {
            float r = 1.f / (1.f + expf(-(xr2.y + gr[1])));
            float z = 1.f / (1.f + expf(-(xz2.y + gz[1])));
            float n = tanhf(xn2.y + r * (gn[1] + bhn1));
            hn1 = (1.f - z) * n + z * hreg[1];
            hreg[1] = hn1;
        }
        const int bG = b0 + bloc;
        const int col = j0 + jj0;
        g_hh[(size_t)(t & 1) * (BH / 2) + (((size_t)bG * H_ + col) >> 1)] = pack2(hn0, hn1);
        if (layer == 0) {
            g_ah[(((size_t)bG * T_ + t) * H_ + col) >> 1] = pack2(hn0, hn1);
        } else if (t == T_ - 1) {
            *(float2*)(final_out + (size_t)bG * H_ + col) = make_float2(hn0, hn1);
        }

        if (t < T_ - 1) grid_bar(barBase + t);
    }
}

// ============================================================================
extern "C" void kernel_launch(void* const* d_in, const int* in_sizes, int n_in,
                              void* d_out, int out_size)
{
    const float* x    = (const float*)d_in[0];
    const float* wih0 = (const float*)d_in[1];
    const float* whh0 = (const float*)d_in[2];
    const float* bih0 = (const float*)d_in[3];
    const float* bhh0 = (const float*)d_in[4];
    const float* wih1 = (const float*)d_in[5];
    const float* whh1 = (const float*)d_in[6];
    const float* bih1 = (const float*)d_in[7];
    const float* bhh1 = (const float*)d_in[8];
    float* out = (float*)d_out;

    cudaFuncSetAttribute(gru_rec, cudaFuncAttributeMaxDynamicSharedMemorySize, REC_SMEM);
    cudaFuncSetAttribute(xg_gemm, cudaFuncAttributeMaxDynamicSharedMemorySize, XG_SMEM);

    uint32_t* ah;  cudaGetSymbolAddress((void**)&ah, g_ah);
    uint32_t* wh;  cudaGetSymbolAddress((void**)&wh, g_wh);

    dim3 gg(G_ / 128, (B_ * T_) / 128);   // 24 x 256

    reset_barriers<<<1, 2 * T_>>>();

    {
        int n4x = B_ * T_ * I_ / 4;
        cvt16<<<(n4x + 255) / 256, 256>>>(x, ah, n4x);
        int n4w = G_ * I_ / 4;
        cvt16<<<(n4w + 255) / 256, 256>>>(wih0, wh, n4w);
    }
    xg_gemm<<<gg, 256, XG_SMEM>>>(ah, wh, bih0, bhh0, I_);
    gru_rec<<<NBLK, NTHR, REC_SMEM>>>(whh0, bhh0, 0, out);   // writes g_ah (fp16 hseq)

    {
        int n4w = G_ * H_ / 4;
        cvt16<<<(n4w + 255) / 256, 256>>>(wih1, wh, n4w);
    }
    xg_gemm<<<gg, 256, XG_SMEM>>>(ah, wh, bih1, bhh1, H_);
    gru_rec<<<NBLK, NTHR, REC_SMEM>>>(whh1, bhh1, 1, out);
}

// round 15
// speedup vs baseline: 1.3881x; 1.3881x over previous
#include <cuda_runtime.h>
#include <cuda_fp16.h>
#include <math.h>
#include <stdint.h>

namespace {
constexpr int B_ = 64;
constexpr int T_ = 512;
constexpr int I_ = 512;
constexpr int H_ = 1024;
constexpr int G_ = 3 * H_;     // 3072
constexpr int NBLK = 128;      // 2 mgroups x 64 colgroups
constexpr int NTHR = 256;
constexpr int BH = B_ * H_;

constexpr int WP = 516;        // W smem row pad (u32)
constexpr int HSP = 516;       // h slice row pad (u32)
constexpr int RPD = 50;        // reduce row pad (floats)
constexpr int WS_U = 48 * WP;
constexpr int HS_U = 32 * HSP;
constexpr int RED_U = 4 * 32 * RPD;
constexpr int REC_SMEM = (WS_U + HS_U + RED_U) * 4;   // 190720 bytes

constexpr int XG_ST = 3;                               // xg pipeline stages
constexpr int XG_SMEM = XG_ST * 128 * 20 * 4 * 2;      // 61440 bytes
}

// Scratch (device globals -- no runtime allocation)
__device__ float g_xg[(size_t)B_ * T_ * G_];            // xg (fp32)
__device__ __align__(16) uint32_t g_ah[(size_t)B_ * T_ * H_ / 2]; // layer input, fp16 pairs
__device__ __align__(16) uint32_t g_wh[(size_t)G_ * H_ / 2];      // w_ih fp16 pairs
__device__ __align__(16) uint32_t g_hh[BH];             // h fp16 pairs, ping-pong
__device__ unsigned g_barcnt[2 * T_];

// ---- helpers ----
__device__ __forceinline__ uint32_t pack2(float x, float y) {
    __half2 h = __floats2half2_rn(x, y);
    return *(uint32_t*)&h;
}
// m16n8k16 fp16 mma, fp32 accum
__device__ __forceinline__ void mma16(float* d, const uint32_t* a, const uint32_t* b) {
    asm volatile(
        "mma.sync.aligned.m16n8k16.row.col.f32.f16.f16.f32 "
        "{%0,%1,%2,%3}, {%4,%5,%6,%7}, {%8,%9}, {%0,%1,%2,%3};"
        : "+f"(d[0]), "+f"(d[1]), "+f"(d[2]), "+f"(d[3])
        : "r"(a[0]), "r"(a[1]), "r"(a[2]), "r"(a[3]), "r"(b[0]), "r"(b[1]));
}
__device__ __forceinline__ uint32_t smem_u32(const void* p) {
    uint32_t a;
    asm("{ .reg .u64 t; cvta.to.shared.u64 t, %1; cvt.u32.u64 %0, t; }" : "=r"(a) : "l"(p));
    return a;
}
__device__ __forceinline__ void cp16(uint32_t d, const uint32_t* s) {
    asm volatile("cp.async.cg.shared.global [%0], [%1], 16;" :: "r"(d), "l"(s) : "memory");
}

// ---- grid barrier (128 arrivals, with fence — measured-good R13 form) ----
__device__ __forceinline__ void grid_bar(unsigned* cnt) {
    __threadfence();
    __syncthreads();
    if (threadIdx.x == 0) {
        asm volatile("red.release.gpu.global.add.u32 [%0], 1;" :: "l"(cnt) : "memory");
        unsigned v;
        do {
            asm volatile("ld.acquire.gpu.global.u32 %0, [%1];" : "=r"(v) : "l"(cnt) : "memory");
        } while (v < (unsigned)NBLK);
    }
    __syncthreads();
}

__global__ void reset_barriers() { g_barcnt[threadIdx.x] = 0; }

// ---- fp32 -> fp16 conversion (vectorized) ----
__global__ __launch_bounds__(256) void cvt16(const float* __restrict__ in,
                                             uint32_t* __restrict__ out, int n4) {
    int i = blockIdx.x * 256 + threadIdx.x;
    if (i < n4) {
        float4 v = ((const float4*)in)[i];
        ((uint2*)out)[i] = make_uint2(pack2(v.x, v.y), pack2(v.z, v.w));
    }
}

// ============================================================================
// xg = A[M][K] @ W[G][K]^T + b_ih (+ b_hh folded for r/z gates)
// fp16 mma.sync m16n8k16, tile 128x128x32, 3-stage cp.async pipeline,
// scalar LDS frag loads (measured-good), ONE sync per chunk (trailing sync
// proven redundant: top sync of iter ch orders mma(ch-1) before issue(ch+2)).
// ============================================================================
__global__ __launch_bounds__(256) void xg_gemm(
    const uint32_t* __restrict__ A,   // [M][K/2]
    const uint32_t* __restrict__ W,   // [G][K/2]
    const float* __restrict__ bih, const float* __restrict__ bhh,
    int K)
{
    extern __shared__ uint32_t smu[];
    uint32_t* sA = smu;                      // [3][128][20]
    uint32_t* sB = smu + XG_ST * 128 * 20;   // [3][128][20]
    const uint32_t sA_b = smem_u32(sA);
    const uint32_t sB_b = smem_u32(sB);

    const int tid = threadIdx.x;
    const int lane = tid & 31, wid = tid >> 5;
    const int gq = lane >> 2, tig = lane & 3;
    const int wm = wid & 3, wn = wid >> 2;
    const int m0 = blockIdx.y * 128, n0 = blockIdx.x * 128;
    const int K2 = K >> 1;
    const int mrow = tid >> 1;
    const int kq = (tid & 1) * 8;

    float acc[2][8][4];
#pragma unroll
    for (int mi = 0; mi < 2; mi++)
#pragma unroll
        for (int ni = 0; ni < 8; ni++)
#pragma unroll
            for (int q = 0; q < 4; q++) acc[mi][ni][q] = 0.f;

    const int nch = K >> 5;                  // 32-k (16-u32) chunks
    const uint32_t dAoff = (uint32_t)((mrow * 20 + kq) * 4);

    auto issue = [&](int ch) {
        const int st = ch % XG_ST;
        const uint32_t sbase = (uint32_t)(st * 128 * 20 * 4);
        const uint32_t* sa = A + (size_t)(m0 + mrow) * K2 + ch * 16 + kq;
        const uint32_t* sb = W + (size_t)(n0 + mrow) * K2 + ch * 16 + kq;
        cp16(sA_b + sbase + dAoff, sa);
        cp16(sA_b + sbase + dAoff + 16, sa + 4);
        cp16(sB_b + sbase + dAoff, sb);
        cp16(sB_b + sbase + dAoff + 16, sb + 4);
        asm volatile("cp.async.commit_group;" ::: "memory");
    };

    issue(0);
    issue(1);

    for (int ch = 0; ch < nch; ch++) {
        if (ch + 1 < nch) asm volatile("cp.async.wait_group 1;" ::: "memory");
        else              asm volatile("cp.async.wait_group 0;" ::: "memory");
        __syncthreads();                     // single barrier per chunk
        if (ch + 2 < nch) issue(ch + 2);

        const uint32_t* bufA = sA + (ch % XG_ST) * 128 * 20;
        const uint32_t* bufB = sB + (ch % XG_ST) * 128 * 20;
#pragma unroll
        for (int s = 0; s < 2; s++) {
            const int c0 = s * 8;
            uint32_t af[2][4];
#pragma unroll
            for (int mi = 0; mi < 2; mi++) {
                int mb = wm * 32 + mi * 16;
                af[mi][0] = bufA[(mb + gq) * 20 + c0 + tig];
                af[mi][1] = bufA[(mb + 8 + gq) * 20 + c0 + tig];
                af[mi][2] = bufA[(mb + gq) * 20 + c0 + tig + 4];
                af[mi][3] = bufA[(mb + 8 + gq) * 20 + c0 + tig + 4];
            }
#pragma unroll
            for (int ni = 0; ni < 8; ni++) {
                int nb = wn * 64 + ni * 8;
                uint32_t bf[2];
                bf[0] = bufB[(nb + gq) * 20 + c0 + tig];
                bf[1] = bufB[(nb + gq) * 20 + c0 + tig + 4];
                mma16(acc[0][ni], af[0], bf);
                mma16(acc[1][ni], af[1], bf);
            }
        }
    }

#pragma unroll
    for (int mi = 0; mi < 2; mi++) {
        int m = m0 + wm * 32 + mi * 16 + gq;
#pragma unroll
        for (int ni = 0; ni < 8; ni++) {
            int n = n0 + wn * 64 + ni * 8 + 2 * tig;
            float b0 = bih[n], b1 = bih[n + 1];
            if (n < 2 * H_) { b0 += bhh[n]; b1 += bhh[n + 1]; }
            *(float2*)(g_xg + (size_t)m * G_ + n) =
                make_float2(acc[mi][ni][0] + b0, acc[mi][ni][1] + b1);
            *(float2*)(g_xg + (size_t)(m + 8) * G_ + n) =
                make_float2(acc[mi][ni][2] + b0, acc[mi][ni][3] + b1);
        }
    }
}

// ============================================================================
// Persistent recurrence (R8/R13 verbatim — best measured config):
// 2D ownership (32 batch rows x 16 cols per block), W_hh slice in smem fp16,
// per step: 2 pipelined 32KB h halves via cp.async, scalar frag LDS,
// 4-way smem reduce, fp32 gates (libm), full 128-block grid barrier.
// ============================================================================
__global__ void __launch_bounds__(NTHR, 1) gru_rec(
    const float* __restrict__ Whh, const float* __restrict__ bhh,
    int layer, float* __restrict__ final_out)
{
    extern __shared__ uint32_t smu[];
    uint32_t* ws = smu;                    // [48][WP]
    uint32_t* hs = smu + WS_U;             // [32][HSP]
    float* red = (float*)(smu + WS_U + HS_U);  // [4][32][RPD]

    const int tid = threadIdx.x;
    const int lane = tid & 31, wid = tid >> 5;
    const int g = lane >> 2, tig = lane & 3;
    const int wk = wid & 3;        // k-quarter (slot interleave s%4==wk)
    const int wn = wid >> 2;       // n half (24 W rows)
    const int cg = blockIdx.x & 63;
    const int mg = blockIdx.x >> 6;
    const int j0 = cg * 16;        // owned cols [j0, j0+16)
    const int b0 = mg * 32;        // owned batch rows [b0, b0+32)
    const uint32_t hs_b = smem_u32(hs);

    // ---- stage W_hh slice (48 rows x 1024) into smem as fp16 (once) ----
    for (int f = tid; f < 48 * 256; f += NTHR) {
        int v = f >> 8, q = f & 255;
        int ni = v >> 4, jj = v & 15;
        const float* wr = Whh + (size_t)(ni * H_ + j0 + jj) * H_ + 4 * q;
        float4 w4 = *(const float4*)wr;
        *(uint2*)(ws + (size_t)v * WP + 2 * q) =
            make_uint2(pack2(w4.x, w4.y), pack2(w4.z, w4.w));
    }
    const int bloc = tid >> 3;                  // local batch row 0..31
    const int jj0 = (tid * 2) & 15;             // even col offset 0..14
    const float bhn0 = bhh[2 * H_ + j0 + jj0];
    const float bhn1 = bhh[2 * H_ + j0 + jj0 + 1];
    float hreg[2] = {0.f, 0.f};
    __syncthreads();

    unsigned* barBase = g_barcnt + layer * T_;
    const int srow = tid >> 3;                  // staging row 0..31
    const int sc0 = (tid & 7) * 4;              // staging u32 col base

    for (int t = 0; t < T_; t++) {
        // prefetch gate inputs (hide latency behind mma pipeline)
        const float* xp = g_xg + ((size_t)(b0 + bloc) * T_ + t) * G_ + j0 + jj0;
        float2 xr2 = *(const float2*)xp;
        float2 xz2 = *(const float2*)(xp + H_);
        float2 xn2 = *(const float2*)(xp + 2 * H_);

        float gr[2] = {0.f, 0.f}, gz[2] = {0.f, 0.f}, gn[2] = {0.f, 0.f};

        if (t > 0) {
            const uint32_t* hre = g_hh + (size_t)((t - 1) & 1) * (BH / 2)
                                  + (size_t)b0 * (H_ / 2);

            float acc[2][3][4];
#pragma unroll
            for (int mt = 0; mt < 2; mt++)
#pragma unroll
                for (int ni = 0; ni < 3; ni++)
#pragma unroll
                    for (int q = 0; q < 4; q++) acc[mt][ni][q] = 0.f;

            // issue both halves of the 32x512(u32) h slice
#pragma unroll
            for (int hh = 0; hh < 2; hh++) {
                uint32_t d = hs_b + (uint32_t)(srow * HSP + hh * 256 + sc0) * 4u;
                const uint32_t* s = hre + (size_t)srow * (H_ / 2) + hh * 256 + sc0;
#pragma unroll
                for (int r = 0; r < 8; r++) {
                    asm volatile("cp.async.cg.shared.global [%0], [%1], 16;"
                                 :: "r"(d + r * 128u), "l"(s + r * 32) : "memory");
                }
                asm volatile("cp.async.commit_group;" ::: "memory");
            }

#pragma unroll
            for (int hh = 0; hh < 2; hh++) {
                if (hh == 0) asm volatile("cp.async.wait_group 1;" ::: "memory");
                else         asm volatile("cp.async.wait_group 0;" ::: "memory");
                __syncthreads();

                // 8 k16 slots for this warp in this half: s = hh*32 + wk + 4*u
#pragma unroll
                for (int u = 0; u < 8; u++) {
                    const int s = hh * 32 + wk + 4 * u;
                    const int c0 = s * 8;
                    uint32_t af[2][4];
#pragma unroll
                    for (int mt = 0; mt < 2; mt++) {
                        const uint32_t* r0 = hs + (size_t)(mt * 16 + g) * HSP + c0 + tig;
                        const uint32_t* r1 = hs + (size_t)(mt * 16 + 8 + g) * HSP + c0 + tig;
                        af[mt][0] = r0[0];
                        af[mt][1] = r1[0];
                        af[mt][2] = r0[4];
                        af[mt][3] = r1[4];
                    }
#pragma unroll
                    for (int ni = 0; ni < 3; ni++) {
                        const uint32_t* br = ws + (size_t)(wn * 24 + ni * 8 + g) * WP + c0 + tig;
                        uint32_t bf[2] = {br[0], br[4]};
                        mma16(acc[0][ni], af[0], bf);
                        mma16(acc[1][ni], af[1], bf);
                    }
                }
            }

            // ---- 4-way k reduce via smem: red[wk][m][n] ----
#pragma unroll
            for (int mt = 0; mt < 2; mt++)
#pragma unroll
                for (int ni = 0; ni < 3; ni++) {
                    int n = wn * 24 + ni * 8 + 2 * tig;
                    float* p0 = red + (size_t)(wk * 32 + mt * 16 + g) * RPD + n;
                    *(float2*)p0 = make_float2(acc[mt][ni][0], acc[mt][ni][1]);
                    float* p1 = red + (size_t)(wk * 32 + mt * 16 + 8 + g) * RPD + n;
                    *(float2*)p1 = make_float2(acc[mt][ni][2], acc[mt][ni][3]);
                }
            __syncthreads();

#pragma unroll
            for (int e = 0; e < 2; e++) {
                int jj = jj0 + e;
#pragma unroll
                for (int p = 0; p < 4; p++) {
                    const float* rp = red + (size_t)(p * 32 + bloc) * RPD;
                    gr[e] += rp[jj];
                    gz[e] += rp[16 + jj];
                    gn[e] += rp[32 + jj];
                }
            }
        }

        // ---- gates: 2 adjacent cols per thread ----
        float hn0, hn1;
        {
            float r = 1.f / (1.f + expf(-(xr2.x + gr[0])));
            float z = 1.f / (1.f + expf(-(xz2.x + gz[0])));
            float n = tanhf(xn2.x + r * (gn[0] + bhn0));
            hn0 = (1.f - z) * n + z * hreg[0];
            hreg[0] = hn0;
        }
        {
            float r = 1.f / (1.f + expf(-(xr2.y + gr[1])));
            float z = 1.f / (1.f + expf(-(xz2.y + gz[1])));
            float n = tanhf(xn2.y + r * (gn[1] + bhn1));
            hn1 = (1.f - z) * n + z * hreg[1];
            hreg[1] = hn1;
        }
        const int bG = b0 + bloc;
        const int col = j0 + jj0;
        g_hh[(size_t)(t & 1) * (BH / 2) + (((size_t)bG * H_ + col) >> 1)] = pack2(hn0, hn1);
        if (layer == 0) {
            g_ah[(((size_t)bG * T_ + t) * H_ + col) >> 1] = pack2(hn0, hn1);
        } else if (t == T_ - 1) {
            *(float2*)(final_out + (size_t)bG * H_ + col) = make_float2(hn0, hn1);
        }

        if (t < T_ - 1) grid_bar(barBase + t);
    }
}

// ============================================================================
extern "C" void kernel_launch(void* const* d_in, const int* in_sizes, int n_in,
                              void* d_out, int out_size)
{
    const float* x    = (const float*)d_in[0];
    const float* wih0 = (const float*)d_in[1];
    const float* whh0 = (const float*)d_in[2];
    const float* bih0 = (const float*)d_in[3];
    const float* bhh0 = (const float*)d_in[4];
    const float* wih1 = (const float*)d_in[5];
    const float* whh1 = (const float*)d_in[6];
    const float* bih1 = (const float*)d_in[7];
    const float* bhh1 = (const float*)d_in[8];
    float* out = (float*)d_out;

    cudaFuncSetAttribute(gru_rec, cudaFuncAttributeMaxDynamicSharedMemorySize, REC_SMEM);
    cudaFuncSetAttribute(xg_gemm, cudaFuncAttributeMaxDynamicSharedMemorySize, XG_SMEM);

    uint32_t* ah;  cudaGetSymbolAddress((void**)&ah, g_ah);
    uint32_t* wh;  cudaGetSymbolAddress((void**)&wh, g_wh);

    dim3 gg(G_ / 128, (B_ * T_) / 128);   // 24 x 256

    reset_barriers<<<1, 2 * T_>>>();

    {
        int n4x = B_ * T_ * I_ / 4;
        cvt16<<<(n4x + 255) / 256, 256>>>(x, ah, n4x);
        int n4w = G_ * I_ / 4;
        cvt16<<<(n4w + 255) / 256, 256>>>(wih0, wh, n4w);
    }
    xg_gemm<<<gg, 256, XG_SMEM>>>(ah, wh, bih0, bhh0, I_);
    gru_rec<<<NBLK, NTHR, REC_SMEM>>>(whh0, bhh0, 0, out);   // writes g_ah (fp16 hseq)

    {
        int n4w = G_ * H_ / 4;
        cvt16<<<(n4w + 255) / 256, 256>>>(wih1, wh, n4w);
    }
    xg_gemm<<<gg, 256, XG_SMEM>>>(ah, wh, bih1, bhh1, H_);
    gru_rec<<<NBLK, NTHR, REC_SMEM>>>(whh1, bhh1, 1, out);
}